// round 11
// baseline (speedup 1.0000x reference)
#include <cuda_runtime.h>
#include <cuda_fp16.h>
#include <cstdint>

#define N_NODES 50000
#define N_EDGES 800000
#define D 128
#define NW 128              // uint32 words per split row (fp16 hi/lo interleaved by col pair)
#define N_GRAPHS 128
#define OUT_DIM 16
#define SLOTS 64            // fixed adjacency slots per node
#define STRA 136            // fp16 row stride for MMA tiles (272B)
#define IMG (128 * STRA)    // fp16 elems per 128x128 W image (34816 B)
#define TM 64               // fused-kernel tile rows
#define NTT 782             // ceil(N_NODES / TM)
#define GRID_F 148          // persistent CTAs
#define FT 512              // fused kernel threads (8 producer + 8 consumer warps)

// ---------------------------------------------------------------------------
// Scratch.  Features: fp16 split-interleaved rows (value = hi + lo).
// ---------------------------------------------------------------------------
__device__ uint32_t g_xs[N_NODES * NW];
__device__ uint32_t g_h1[N_NODES * NW];
__device__ uint32_t g_h2[N_NODES * NW];
__device__ float g_sums[N_GRAPHS * D];
__device__ float g_cnt[N_GRAPHS];
__device__ int g_deg[N_NODES];
__device__ int g_adj[N_NODES * SLOTS];
__device__ __align__(16) __half g_Wf16[3 * 2 * IMG];   // per layer: [rel][root]

// ---------------------------------------------------------------------------
// Helpers
// ---------------------------------------------------------------------------
__device__ __forceinline__ uint32_t smem_u32(const void* p) {
    uint32_t a;
    asm("{ .reg .u64 t; cvta.to.shared.u64 t, %1; cvt.u32.u64 %0, t; }"
        : "=r"(a) : "l"(p));
    return a;
}
__device__ __forceinline__ float2 up2(uint32_t w) {    // packed fp16x2 -> f32x2
    float2 f;
    asm("{ .reg .f16 h0, h1; mov.b32 {h0, h1}, %2;\n\t"
        "  cvt.f32.f16 %0, h0; cvt.f32.f16 %1, h1; }"
        : "=f"(f.x), "=f"(f.y) : "r"(w));
    return f;
}
__device__ __forceinline__ uint32_t packh2(float a, float b) {  // a->lo, b->hi
    uint32_t r;
    asm("cvt.rn.f16x2.f32 %0, %1, %2;" : "=r"(r) : "f"(b), "f"(a));
    return r;
}
__device__ __forceinline__ uint2 split2h(float a, float b) {
    uint32_t hw = packh2(a, b);
    float2 h = up2(hw);
    uint32_t lw = packh2(a - h.x, b - h.y);
    return make_uint2(hw, lw);
}
__device__ __forceinline__ void ldsm4(uint32_t* r, uint32_t addr) {
    asm volatile("ldmatrix.sync.aligned.m8n8.x4.shared.b16 {%0,%1,%2,%3}, [%4];"
                 : "=r"(r[0]), "=r"(r[1]), "=r"(r[2]), "=r"(r[3]) : "r"(addr));
}
__device__ __forceinline__ void mma16816h(float* c, const uint32_t* a,
                                          uint32_t b0, uint32_t b1) {
    asm volatile(
        "mma.sync.aligned.m16n8k16.row.col.f32.f16.f16.f32 "
        "{%0,%1,%2,%3}, {%4,%5,%6,%7}, {%8,%9}, {%0,%1,%2,%3};"
        : "+f"(c[0]), "+f"(c[1]), "+f"(c[2]), "+f"(c[3])
        : "r"(a[0]), "r"(a[1]), "r"(a[2]), "r"(a[3]), "r"(b0), "r"(b1));
}
__device__ __forceinline__ void bar_sync(int id) {
    asm volatile("bar.sync %0, %1;" :: "r"(id), "r"(FT) : "memory");
}
__device__ __forceinline__ void bar_arrive(int id) {
    asm volatile("bar.arrive %0, %1;" :: "r"(id), "r"(FT) : "memory");
}

// ---------------------------------------------------------------------------
// Setup
// ---------------------------------------------------------------------------
__global__ void k_setup(const float* __restrict__ x) {
    int i = blockIdx.x * blockDim.x + threadIdx.x;
    if (i < N_NODES) g_deg[i] = 0;
    if (i < N_GRAPHS * D) g_sums[i] = 0.f;
    if (i < N_GRAPHS) g_cnt[i] = 0.f;
    if (i < N_NODES * 32) {
        int node = i >> 5;
        int t4 = i & 31;
        float4 v = *reinterpret_cast<const float4*>(x + (size_t)node * D + t4 * 4);
        uint2 p0 = split2h(v.x, v.y);
        uint2 p1 = split2h(v.z, v.w);
        *reinterpret_cast<uint4*>(g_xs + (size_t)node * NW + t4 * 4) =
            make_uint4(p0.x, p0.y, p1.x, p1.y);
    }
}

__global__ void k_fill(const int* __restrict__ ei) {
    int e = blockIdx.x * blockDim.x + threadIdx.x;
    if (e < N_EDGES) {
        int dst = ei[N_EDGES + e];
        int p = atomicAdd(&g_deg[dst], 1);
        if (p < SLOTS) g_adj[dst * SLOTS + p] = ei[e];
    }
}

__global__ __launch_bounds__(256) void k_wprep(const float* __restrict__ Wrel,
                                               const float* __restrict__ Wroot) {
    int m = blockIdx.x;                       // layer*2 + isroot
    const float* W = ((m & 1) ? Wroot : Wrel) + (m >> 1) * D * D;
    __half* dst = g_Wf16 + m * IMG;
    for (int i = threadIdx.x; i < D * D; i += 256) {
        int n = i & 127;
        int k = i >> 7;
        dst[n * STRA + k] = __float2half(W[k * D + n]);
    }
}

// ---------------------------------------------------------------------------
// Fused gather+GEMM, persistent, warp-specialized, double-buffered.
//   hout = split( relu( agg@Wrel + hin@Wroot + b ) )
// SMEM: W 2*34816 | bias 512 | 2 x tile-set {AggHi,AggLo,HHi,HLo} (4*17408)
// ---------------------------------------------------------------------------
#define SMB_BIAS 69632
#define SMB_TS   70144
#define TS_SIZE  69632
#define TS_AGG_HI 0
#define TS_AGG_LO 17408
#define TS_H_HI   34816
#define TS_H_LO   52224
#define SM_TOTAL 209408     // 70144 + 2*69632

// One K=128 pass: c += (Ahi + Alo) @ W   (A planes at aHi/aLo, warp tile 32x32)
__device__ __forceinline__ void mma_pass(float c[2][4][4], uint32_t aHi,
                                         uint32_t aLo, uint32_t wBase,
                                         int mrow0, int ncol0, int lane) {
    int arow = (lane & 7) + ((lane >> 3) & 1) * 8;
    int akc = ((lane >> 4) & 1) * 8;
    int bn = (lane & 7) + ((lane >> 4) & 1) * 8;
    int bkc = ((lane >> 3) & 1) * 8;
#pragma unroll
    for (int ks = 0; ks < 8; ks++) {
        int k0 = ks * 16;
        uint32_t fHi[2][4], fLo[2][4];
#pragma unroll
        for (int mt = 0; mt < 2; mt++) {
            uint32_t off = (uint32_t)((mrow0 + mt * 16 + arow) * (STRA * 2) +
                                      (k0 + akc) * 2);
            ldsm4(fHi[mt], aHi + off);
            ldsm4(fLo[mt], aLo + off);
        }
#pragma unroll
        for (int np = 0; np < 2; np++) {
            uint32_t woff = (uint32_t)((ncol0 + np * 16 + bn) * (STRA * 2) +
                                       (k0 + bkc) * 2);
            uint32_t b[4];
            ldsm4(b, wBase + woff);
#pragma unroll
            for (int mt = 0; mt < 2; mt++) {
                mma16816h(c[mt][np * 2], fHi[mt], b[0], b[1]);
                mma16816h(c[mt][np * 2 + 1], fHi[mt], b[2], b[3]);
                mma16816h(c[mt][np * 2], fLo[mt], b[0], b[1]);
                mma16816h(c[mt][np * 2 + 1], fLo[mt], b[2], b[3]);
            }
        }
    }
}

__global__ __launch_bounds__(FT, 1)
void k_fused(const uint32_t* __restrict__ hin,
             const __half* __restrict__ wlayer,
             const float* __restrict__ bias,
             uint32_t* __restrict__ hout) {
    extern __shared__ char smem[];
    int tid = threadIdx.x;
    int w = tid >> 5;
    int lane = tid & 31;
    uint32_t sbase = smem_u32(smem);

    // Weights + bias (all 512 threads)
    {
        const float4* s4 = reinterpret_cast<const float4*>(wlayer);
        float4* d4 = reinterpret_cast<float4*>(smem);
        for (int i = tid; i < 4352; i += FT) d4[i] = s4[i];
        if (tid < 128) ((float*)(smem + SMB_BIAS))[tid] = bias[tid];
    }
    __syncthreads();

    if (w >= 8) {
        // ---------------- Producer warps (8-15): gather + H copy ----------
        int pw = w - 8;
        int it = 0;
        for (int tile = blockIdx.x; tile < NTT; tile += GRID_F, it++) {
            int b = it & 1;
            if (it >= 2) bar_sync(3 + b);            // wait EMPTY[b]
            char* ts = smem + SMB_TS + b * TS_SIZE;
            uint32_t* aggHi = (uint32_t*)(ts + TS_AGG_HI);
            uint32_t* aggLo = (uint32_t*)(ts + TS_AGG_LO);
            uint32_t* hHi = (uint32_t*)(ts + TS_H_HI);
            uint32_t* hLo = (uint32_t*)(ts + TS_H_LO);
            int row0 = tile * TM;
#pragma unroll
            for (int rr = 0; rr < 8; rr++) {
                int r = pw * 8 + rr;
                int n = row0 + r;
                float a0 = 0.f, a1 = 0.f, a2 = 0.f, a3 = 0.f;
                uint4 hrow = make_uint4(0u, 0u, 0u, 0u);
                if (n < N_NODES) {
                    hrow = *reinterpret_cast<const uint4*>(
                        hin + (size_t)n * NW + lane * 4);
                    int deg = g_deg[n];
                    if (deg > SLOTS) deg = SLOTS;
                    const int* adj = g_adj + n * SLOTS;
                    int i = 0;
                    for (; i + 4 <= deg; i += 4) {
#pragma unroll
                        for (int j = 0; j < 4; j++) {
                            int s = adj[i + j];
                            uint4 u = *reinterpret_cast<const uint4*>(
                                hin + (size_t)s * NW + lane * 4);
                            float2 h0 = up2(u.x), l0 = up2(u.y);
                            float2 h1 = up2(u.z), l1 = up2(u.w);
                            a0 += h0.x + l0.x;
                            a1 += h0.y + l0.y;
                            a2 += h1.x + l1.x;
                            a3 += h1.y + l1.y;
                        }
                    }
                    for (; i < deg; i++) {
                        int s = adj[i];
                        uint4 u = *reinterpret_cast<const uint4*>(
                            hin + (size_t)s * NW + lane * 4);
                        float2 h0 = up2(u.x), l0 = up2(u.y);
                        float2 h1 = up2(u.z), l1 = up2(u.w);
                        a0 += h0.x + l0.x;
                        a1 += h0.y + l0.y;
                        a2 += h1.x + l1.x;
                        a3 += h1.y + l1.y;
                    }
                }
                uint2 p0 = split2h(a0, a1);
                uint2 p1 = split2h(a2, a3);
                int wo = r * 68 + lane * 2;
                *reinterpret_cast<uint2*>(aggHi + wo) = make_uint2(p0.x, p1.x);
                *reinterpret_cast<uint2*>(aggLo + wo) = make_uint2(p0.y, p1.y);
                *reinterpret_cast<uint2*>(hHi + wo) = make_uint2(hrow.x, hrow.z);
                *reinterpret_cast<uint2*>(hLo + wo) = make_uint2(hrow.y, hrow.w);
            }
            __threadfence_block();
            bar_arrive(1 + b);                       // signal FULL[b]
        }
    } else {
        // ---------------- Consumer warps (0-7): MMA + epilogue ------------
        int mrow0 = (w & 1) * 32;
        int ncol0 = (w >> 1) * 32;
        const float* sb = (const float*)(smem + SMB_BIAS);
        int g = lane >> 2;
        int t = lane & 3;
        int it = 0;
        for (int tile = blockIdx.x; tile < NTT; tile += GRID_F, it++) {
            int b = it & 1;
            bar_sync(1 + b);                         // wait FULL[b]
            uint32_t ts = sbase + SMB_TS + b * TS_SIZE;
            int row0 = tile * TM;

            float c[2][4][4];
#pragma unroll
            for (int mt = 0; mt < 2; mt++)
#pragma unroll
                for (int nt = 0; nt < 4; nt++)
#pragma unroll
                    for (int i = 0; i < 4; i++) c[mt][nt][i] = 0.f;

            mma_pass(c, ts + TS_AGG_HI, ts + TS_AGG_LO, sbase, mrow0, ncol0, lane);
            mma_pass(c, ts + TS_H_HI, ts + TS_H_LO, sbase + 34816u, mrow0, ncol0,
                     lane);

            bar_arrive(3 + b);                       // signal EMPTY[b]

            // Epilogue (registers only; buffer already released)
#pragma unroll
            for (int mt = 0; mt < 2; mt++) {
#pragma unroll
                for (int nt = 0; nt < 4; nt++) {
                    int col = ncol0 + nt * 8 + t * 2;
                    float b0 = sb[col], b1 = sb[col + 1];
                    int r0 = row0 + mrow0 + mt * 16 + g;
                    if (r0 < N_NODES) {
                        uint2 p = split2h(fmaxf(c[mt][nt][0] + b0, 0.f),
                                          fmaxf(c[mt][nt][1] + b1, 0.f));
                        *reinterpret_cast<uint2*>(hout + (size_t)r0 * NW + col) = p;
                    }
                    int r1 = r0 + 8;
                    if (r1 < N_NODES) {
                        uint2 p = split2h(fmaxf(c[mt][nt][2] + b0, 0.f),
                                          fmaxf(c[mt][nt][3] + b1, 0.f));
                        *reinterpret_cast<uint2*>(hout + (size_t)r1 * NW + col) = p;
                    }
                }
            }
        }
    }
}

// ---------------------------------------------------------------------------
// Pool (reads fp16 split) + head
// ---------------------------------------------------------------------------
#define NODES_PER_WARP 4
__global__ __launch_bounds__(256) void k_pool(const uint32_t* __restrict__ h,
                                              const int* __restrict__ batch) {
    int gwarp = (blockIdx.x * blockDim.x + threadIdx.x) >> 5;
    int lane = threadIdx.x & 31;
#pragma unroll
    for (int i = 0; i < NODES_PER_WARP; i++) {
        int n = gwarp * NODES_PER_WARP + i;
        if (n >= N_NODES) return;
        int g = batch[n];
        uint4 u = *reinterpret_cast<const uint4*>(h + (size_t)n * NW + lane * 4);
        float2 h0 = up2(u.x), l0 = up2(u.y), h1 = up2(u.z), l1 = up2(u.w);
        float v0 = h0.x + l0.x;
        float v1 = h0.y + l0.y;
        float v2 = h1.x + l1.x;
        float v3 = h1.y + l1.y;
        float* dp = g_sums + g * D + lane * 4;
        asm volatile("red.global.add.v4.f32 [%0], {%1,%2,%3,%4};"
                     :: "l"(dp), "f"(v0), "f"(v1), "f"(v2), "f"(v3)
                     : "memory");
        if (lane == 0) atomicAdd(&g_cnt[g], 1.0f);
    }
}

__global__ __launch_bounds__(128) void k_head(const float* __restrict__ W1,
                                              const float* __restrict__ b1,
                                              const float* __restrict__ W2,
                                              const float* __restrict__ b2,
                                              float* __restrict__ out) {
    __shared__ float pooled[D];
    __shared__ float t[D];
    int g = blockIdx.x;
    int tid = threadIdx.x;
    float cnt = fmaxf(g_cnt[g], 1.0f);
    pooled[tid] = g_sums[g * D + tid] / cnt;
    __syncthreads();

    float acc = b1[tid];
#pragma unroll 8
    for (int k = 0; k < D; k++) acc += pooled[k] * W1[k * D + tid];
    t[tid] = acc;
    __syncthreads();

    if (tid < OUT_DIM) {
        float o = b2[tid];
#pragma unroll 8
        for (int k = 0; k < D; k++) o += t[k] * W2[k * OUT_DIM + tid];
        out[g * OUT_DIM + tid] = o;
    }
}

// ---------------------------------------------------------------------------
// Launch sequence (graph-capturable)
// ---------------------------------------------------------------------------
extern "C" void kernel_launch(void* const* d_in, const int* in_sizes, int n_in,
                              void* d_out, int out_size) {
    const float* x = (const float*)d_in[0];
    const int* ei = (const int*)d_in[1];      // int32 (JAX x64 disabled)
    const int* batch = (const int*)d_in[2];   // int32
    const float* Wrel = (const float*)d_in[3];
    const float* brel = (const float*)d_in[4];
    const float* Wroot = (const float*)d_in[5];
    const float* W1 = (const float*)d_in[6];
    const float* b1 = (const float*)d_in[7];
    const float* W2 = (const float*)d_in[8];
    const float* b2 = (const float*)d_in[9];
    float* out = (float*)d_out;

    cudaFuncSetAttribute(k_fused, cudaFuncAttributeMaxDynamicSharedMemorySize,
                         SM_TOTAL);

    uint32_t *xs, *h1, *h2;
    __half* wfp;
    cudaGetSymbolAddress((void**)&xs, g_xs);
    cudaGetSymbolAddress((void**)&h1, g_h1);
    cudaGetSymbolAddress((void**)&h2, g_h2);
    cudaGetSymbolAddress((void**)&wfp, g_Wf16);

    const int setup_blocks = (N_NODES * 32 + 255) / 256;
    const int edge_blocks = (N_EDGES + 255) / 256;
    const int pool_blocks = (N_NODES + 8 * NODES_PER_WARP - 1) / (8 * NODES_PER_WARP);

    k_setup<<<setup_blocks, 256>>>(x);
    k_wprep<<<6, 256>>>(Wrel, Wroot);
    k_fill<<<edge_blocks, 256>>>(ei);

    k_fused<<<GRID_F, FT, SM_TOTAL>>>(xs, wfp + 0 * 2 * IMG, brel, h1);
    k_fused<<<GRID_F, FT, SM_TOTAL>>>(h1, wfp + 1 * 2 * IMG, brel + D, h2);
    k_fused<<<GRID_F, FT, SM_TOTAL>>>(h2, wfp + 2 * 2 * IMG, brel + 2 * D, h1);

    k_pool<<<pool_blocks, 256>>>(h1, batch);
    k_head<<<N_GRAPHS, 128>>>(W1, b1, W2, b2, out);
}

// round 12
// speedup vs baseline: 2.2975x; 2.2975x over previous
#include <cuda_runtime.h>
#include <cuda_fp16.h>
#include <cstdint>

#define N_NODES 50000
#define N_EDGES 800000
#define D 128
#define NW2 64              // uint32 words per plain-fp16 row (256 B)
#define N_GRAPHS 128
#define OUT_DIM 16
#define SLOTS 64            // fixed adjacency slots per node (Poisson(16), P(>64)~1e-20)
#define STRA 136            // fp16 row stride for MMA tiles (272B: conflict-free ldmatrix)
#define IMG (128 * STRA)    // fp16 elems per 128x128 W image (34816 B)
#define NT 391              // 128-row tiles covering N_NODES
#define GRID_GEMM 148       // persistent CTAs
#define GT 512              // GEMM threads (16 warps)

// ---------------------------------------------------------------------------
// Scratch.  Features: plain fp16 rows, 64 words (256 B) each.
// ---------------------------------------------------------------------------
__device__ uint32_t g_xs[N_NODES * NW2];
__device__ uint32_t g_aggs[N_NODES * NW2];
__device__ uint32_t g_h1[N_NODES * NW2];
__device__ uint32_t g_h2[N_NODES * NW2];
__device__ float g_sums[N_GRAPHS * D];
__device__ float g_cnt[N_GRAPHS];
__device__ int g_deg[N_NODES];
__device__ int g_adj[N_NODES * SLOTS];
__device__ __align__(16) __half g_Wf16[3 * 2 * IMG];   // per layer: [rel][root]

// ---------------------------------------------------------------------------
// Helpers
// ---------------------------------------------------------------------------
__device__ __forceinline__ uint32_t smem_u32(const void* p) {
    uint32_t a;
    asm("{ .reg .u64 t; cvta.to.shared.u64 t, %1; cvt.u32.u64 %0, t; }"
        : "=r"(a) : "l"(p));
    return a;
}
__device__ __forceinline__ float2 up2(uint32_t w) {    // packed fp16x2 -> f32x2
    float2 f;
    asm("{ .reg .f16 h0, h1; mov.b32 {h0, h1}, %2;\n\t"
        "  cvt.f32.f16 %0, h0; cvt.f32.f16 %1, h1; }"
        : "=f"(f.x), "=f"(f.y) : "r"(w));
    return f;
}
__device__ __forceinline__ uint32_t packh2(float a, float b) {  // a->lo, b->hi
    uint32_t r;
    asm("cvt.rn.f16x2.f32 %0, %1, %2;" : "=r"(r) : "f"(b), "f"(a));
    return r;
}
__device__ __forceinline__ void ldsm4(uint32_t* r, uint32_t addr) {
    asm volatile("ldmatrix.sync.aligned.m8n8.x4.shared.b16 {%0,%1,%2,%3}, [%4];"
                 : "=r"(r[0]), "=r"(r[1]), "=r"(r[2]), "=r"(r[3]) : "r"(addr));
}
__device__ __forceinline__ void mma16816h(float* c, const uint32_t* a,
                                          uint32_t b0, uint32_t b1) {
    asm volatile(
        "mma.sync.aligned.m16n8k16.row.col.f32.f16.f16.f32 "
        "{%0,%1,%2,%3}, {%4,%5,%6,%7}, {%8,%9}, {%0,%1,%2,%3};"
        : "+f"(c[0]), "+f"(c[1]), "+f"(c[2]), "+f"(c[3])
        : "r"(a[0]), "r"(a[1]), "r"(a[2]), "r"(a[3]), "r"(b0), "r"(b1));
}

// ---------------------------------------------------------------------------
// Setup: zero deg/pool, convert x -> plain fp16
// ---------------------------------------------------------------------------
__global__ void k_setup(const float* __restrict__ x) {
    int i = blockIdx.x * blockDim.x + threadIdx.x;
    if (i < N_NODES) g_deg[i] = 0;
    if (i < N_GRAPHS * D) g_sums[i] = 0.f;
    if (i < N_GRAPHS) g_cnt[i] = 0.f;
    if (i < N_NODES * 32) {
        int node = i >> 5;
        int t4 = i & 31;
        float4 v = *reinterpret_cast<const float4*>(x + (size_t)node * D + t4 * 4);
        *reinterpret_cast<uint2*>(g_xs + (size_t)node * NW2 + t4 * 2) =
            make_uint2(packh2(v.x, v.y), packh2(v.z, v.w));
    }
}

__global__ void k_fill(const int* __restrict__ ei) {
    int e = blockIdx.x * blockDim.x + threadIdx.x;
    if (e < N_EDGES) {
        int dst = ei[N_EDGES + e];
        int p = atomicAdd(&g_deg[dst], 1);
        if (p < SLOTS) g_adj[dst * SLOTS + p] = ei[e];
    }
}

// W (k-major [k][n]) -> single fp16 image, transposed to [n][k], stride STRA.
__global__ __launch_bounds__(256) void k_wprep(const float* __restrict__ Wrel,
                                               const float* __restrict__ Wroot) {
    int m = blockIdx.x;                       // layer*2 + isroot
    const float* W = ((m & 1) ? Wroot : Wrel) + (m >> 1) * D * D;
    __half* dst = g_Wf16 + m * IMG;
    for (int i = threadIdx.x; i < D * D; i += 256) {
        int n = i & 127;
        int k = i >> 7;
        dst[n * STRA + k] = __float2half(W[k * D + n]);
    }
}

// ---------------------------------------------------------------------------
// Gather: aggs[n] = fp16( sum_{s in adj(n)} h[s] ).  One warp/node; lane = uint2.
// ---------------------------------------------------------------------------
__global__ __launch_bounds__(256) void k_gather(const uint32_t* __restrict__ h) {
    int n = (blockIdx.x * blockDim.x + threadIdx.x) >> 5;
    if (n >= N_NODES) return;
    int lane = threadIdx.x & 31;
    int deg = g_deg[n];
    if (deg > SLOTS) deg = SLOTS;
    const int* adj = g_adj + n * SLOTS;
    float a0 = 0.f, a1 = 0.f, a2 = 0.f, a3 = 0.f;
    int i = 0;
    for (; i + 4 <= deg; i += 4) {
#pragma unroll
        for (int j = 0; j < 4; j++) {
            int s = adj[i + j];
            uint2 u = *reinterpret_cast<const uint2*>(h + (size_t)s * NW2 + lane * 2);
            float2 f0 = up2(u.x), f1 = up2(u.y);
            a0 += f0.x; a1 += f0.y; a2 += f1.x; a3 += f1.y;
        }
    }
    for (; i < deg; i++) {
        int s = adj[i];
        uint2 u = *reinterpret_cast<const uint2*>(h + (size_t)s * NW2 + lane * 2);
        float2 f0 = up2(u.x), f1 = up2(u.y);
        a0 += f0.x; a1 += f0.y; a2 += f1.x; a3 += f1.y;
    }
    *reinterpret_cast<uint2*>(g_aggs + (size_t)n * NW2 + lane * 2) =
        make_uint2(packh2(a0, a1), packh2(a2, a3));
}

// ---------------------------------------------------------------------------
// Persistent HMMA GraphConv GEMM, single fp16 product per operand:
//   hout = fp16( relu( agg@Wrel + hin@Wroot + b ) )
// 148 CTAs x 512 thr (16 warps, warp tile 32m x 32n), loop over 391 tiles.
// SMEM: W 2*34816 | bias 512 | A 34816  = 104960 B
// ---------------------------------------------------------------------------
#define SMB_BIAS 69632
#define SMB_A    70144
#define SM_TOTAL 104960

// Copy one 128-row plain-fp16 tile into A smem (stride STRA halfs = 68 words).
__device__ __forceinline__ void copyA(const uint32_t* __restrict__ src, int row0,
                                      char* smem) {
    uint32_t* aP = reinterpret_cast<uint32_t*>(smem + SMB_A);
#pragma unroll
    for (int it = 0; it < 8; it++) {
        int idx = it * GT + threadIdx.x;
        int row = idx >> 5;
        int t2 = idx & 31;
        int grow = row0 + row;
        uint2 u = make_uint2(0u, 0u);
        if (grow < N_NODES)
            u = *reinterpret_cast<const uint2*>(src + (size_t)grow * NW2 + t2 * 2);
        *reinterpret_cast<uint2*>(aP + row * 68 + t2 * 2) = u;
    }
}

// One K=128 pass: c += A @ W[wimg]
__device__ __forceinline__ void mma_pass(float c[2][4][4], uint32_t sbase,
                                         int wimg, int mrow0, int ncol0, int lane) {
    uint32_t aBase = sbase + SMB_A;
    uint32_t wBase = sbase + (uint32_t)(wimg * 34816);
    int arow = (lane & 7) + ((lane >> 3) & 1) * 8;
    int akc = ((lane >> 4) & 1) * 8;
    int bn = (lane & 7) + ((lane >> 4) & 1) * 8;
    int bkc = ((lane >> 3) & 1) * 8;

#pragma unroll
    for (int ks = 0; ks < 8; ks++) {
        int k0 = ks * 16;
        uint32_t a[2][4];
#pragma unroll
        for (int mt = 0; mt < 2; mt++) {
            uint32_t off = (uint32_t)((mrow0 + mt * 16 + arow) * (STRA * 2) +
                                      (k0 + akc) * 2);
            ldsm4(a[mt], aBase + off);
        }
#pragma unroll
        for (int np = 0; np < 2; np++) {
            uint32_t woff = (uint32_t)((ncol0 + np * 16 + bn) * (STRA * 2) +
                                       (k0 + bkc) * 2);
            uint32_t b[4];
            ldsm4(b, wBase + woff);
#pragma unroll
            for (int mt = 0; mt < 2; mt++) {
                mma16816h(c[mt][np * 2], a[mt], b[0], b[1]);
                mma16816h(c[mt][np * 2 + 1], a[mt], b[2], b[3]);
            }
        }
    }
}

__global__ __launch_bounds__(GT, 1)
void k_gemm_mma(const uint32_t* __restrict__ hin,
                const __half* __restrict__ wlayer,   // [rel][root] images
                const float* __restrict__ bias,
                uint32_t* __restrict__ hout) {
    extern __shared__ char smem[];
    int tid = threadIdx.x;
    int w = tid >> 5;
    int lane = tid & 31;
    int mrow0 = (w & 3) * 32;        // 4 m-warps
    int ncol0 = (w >> 2) * 32;       // 4 n-warps
    uint32_t sbase = smem_u32(smem);

    // Weights once per CTA (69632 B)
    {
        const float4* s4 = reinterpret_cast<const float4*>(wlayer);
        float4* d4 = reinterpret_cast<float4*>(smem);
        for (int i = tid; i < 4352; i += GT) d4[i] = s4[i];
    }
    if (tid < 128) ((float*)(smem + SMB_BIAS))[tid] = bias[tid];
    __syncthreads();

    const float* sb = (const float*)(smem + SMB_BIAS);
    int g = lane >> 2;
    int t = lane & 3;

    for (int tile = blockIdx.x; tile < NT; tile += GRID_GEMM) {
        int row0 = tile * 128;

        copyA(g_aggs, row0, smem);
        __syncthreads();

        float c[2][4][4];
#pragma unroll
        for (int mt = 0; mt < 2; mt++)
#pragma unroll
            for (int nt = 0; nt < 4; nt++)
#pragma unroll
                for (int i = 0; i < 4; i++) c[mt][nt][i] = 0.f;

        mma_pass(c, sbase, 0, mrow0, ncol0, lane);   // agg @ Wrel
        __syncthreads();
        copyA(hin, row0, smem);
        __syncthreads();
        mma_pass(c, sbase, 1, mrow0, ncol0, lane);   // hin @ Wroot

        // Epilogue: bias + relu, write plain fp16
#pragma unroll
        for (int mt = 0; mt < 2; mt++) {
#pragma unroll
            for (int nt = 0; nt < 4; nt++) {
                int col = ncol0 + nt * 8 + t * 2;
                float b0 = sb[col], b1 = sb[col + 1];
                int r0 = row0 + mrow0 + mt * 16 + g;
                if (r0 < N_NODES) {
                    hout[(size_t)r0 * NW2 + (col >> 1)] =
                        packh2(fmaxf(c[mt][nt][0] + b0, 0.f),
                               fmaxf(c[mt][nt][1] + b1, 0.f));
                }
                int r1 = r0 + 8;
                if (r1 < N_NODES) {
                    hout[(size_t)r1 * NW2 + (col >> 1)] =
                        packh2(fmaxf(c[mt][nt][2] + b0, 0.f),
                               fmaxf(c[mt][nt][3] + b1, 0.f));
                }
            }
        }
        __syncthreads();
    }
}

// ---------------------------------------------------------------------------
// Pool (reads plain fp16) + head
// ---------------------------------------------------------------------------
#define NODES_PER_WARP 4
__global__ __launch_bounds__(256) void k_pool(const uint32_t* __restrict__ h,
                                              const int* __restrict__ batch) {
    int gwarp = (blockIdx.x * blockDim.x + threadIdx.x) >> 5;
    int lane = threadIdx.x & 31;
#pragma unroll
    for (int i = 0; i < NODES_PER_WARP; i++) {
        int n = gwarp * NODES_PER_WARP + i;
        if (n >= N_NODES) return;
        int g = batch[n];
        uint2 u = *reinterpret_cast<const uint2*>(h + (size_t)n * NW2 + lane * 2);
        float2 f0 = up2(u.x), f1 = up2(u.y);
        float* dp = g_sums + g * D + lane * 4;
        asm volatile("red.global.add.v4.f32 [%0], {%1,%2,%3,%4};"
                     :: "l"(dp), "f"(f0.x), "f"(f0.y), "f"(f1.x), "f"(f1.y)
                     : "memory");
        if (lane == 0) atomicAdd(&g_cnt[g], 1.0f);
    }
}

__global__ __launch_bounds__(128) void k_head(const float* __restrict__ W1,
                                              const float* __restrict__ b1,
                                              const float* __restrict__ W2,
                                              const float* __restrict__ b2,
                                              float* __restrict__ out) {
    __shared__ float pooled[D];
    __shared__ float t[D];
    int g = blockIdx.x;
    int tid = threadIdx.x;
    float cnt = fmaxf(g_cnt[g], 1.0f);
    pooled[tid] = g_sums[g * D + tid] / cnt;
    __syncthreads();

    float acc = b1[tid];
#pragma unroll 8
    for (int k = 0; k < D; k++) acc += pooled[k] * W1[k * D + tid];
    t[tid] = acc;
    __syncthreads();

    if (tid < OUT_DIM) {
        float o = b2[tid];
#pragma unroll 8
        for (int k = 0; k < D; k++) o += t[k] * W2[k * OUT_DIM + tid];
        out[g * OUT_DIM + tid] = o;
    }
}

// ---------------------------------------------------------------------------
// Launch sequence (graph-capturable)
// ---------------------------------------------------------------------------
extern "C" void kernel_launch(void* const* d_in, const int* in_sizes, int n_in,
                              void* d_out, int out_size) {
    const float* x = (const float*)d_in[0];
    const int* ei = (const int*)d_in[1];      // int32 (JAX x64 disabled)
    const int* batch = (const int*)d_in[2];   // int32
    const float* Wrel = (const float*)d_in[3];
    const float* brel = (const float*)d_in[4];
    const float* Wroot = (const float*)d_in[5];
    const float* W1 = (const float*)d_in[6];
    const float* b1 = (const float*)d_in[7];
    const float* W2 = (const float*)d_in[8];
    const float* b2 = (const float*)d_in[9];
    float* out = (float*)d_out;

    cudaFuncSetAttribute(k_gemm_mma, cudaFuncAttributeMaxDynamicSharedMemorySize,
                         SM_TOTAL);

    uint32_t *xs, *h1, *h2;
    __half* wfp;
    cudaGetSymbolAddress((void**)&xs, g_xs);
    cudaGetSymbolAddress((void**)&h1, g_h1);
    cudaGetSymbolAddress((void**)&h2, g_h2);
    cudaGetSymbolAddress((void**)&wfp, g_Wf16);

    const int setup_blocks = (N_NODES * 32 + 255) / 256;
    const int edge_blocks = (N_EDGES + 255) / 256;
    const int gather_blocks = (N_NODES + 7) / 8;
    const int pool_blocks = (N_NODES + 8 * NODES_PER_WARP - 1) / (8 * NODES_PER_WARP);

    // Setup
    k_setup<<<setup_blocks, 256>>>(x);
    k_wprep<<<6, 256>>>(Wrel, Wroot);
    k_fill<<<edge_blocks, 256>>>(ei);

    // Layer 0: xs -> h1
    k_gather<<<gather_blocks, 256>>>(xs);
    k_gemm_mma<<<GRID_GEMM, GT, SM_TOTAL>>>(xs, wfp + 0 * 2 * IMG, brel, h1);
    // Layer 1: h1 -> h2
    k_gather<<<gather_blocks, 256>>>(h1);
    k_gemm_mma<<<GRID_GEMM, GT, SM_TOTAL>>>(h1, wfp + 1 * 2 * IMG, brel + D, h2);
    // Layer 2: h2 -> h1
    k_gather<<<gather_blocks, 256>>>(h2);
    k_gemm_mma<<<GRID_GEMM, GT, SM_TOTAL>>>(h2, wfp + 2 * 2 * IMG, brel + 2 * D, h1);

    // Pool + head
    k_pool<<<pool_blocks, 256>>>(h1, batch);
    k_head<<<N_GRAPHS, 128>>>(W1, b1, W2, b2, out);
}

// round 13
// speedup vs baseline: 2.3016x; 1.0018x over previous
#include <cuda_runtime.h>
#include <cuda_fp16.h>
#include <cstdint>

#define N_NODES 50000
#define N_EDGES 800000
#define D 128
#define NW2 64              // uint32 words per plain-fp16 row (256 B)
#define N_GRAPHS 128
#define OUT_DIM 16
#define SLOTS 64            // fixed adjacency slots per node (Poisson(16), P(>64)~1e-20)
#define STRA 136            // fp16 row stride for MMA tiles (272B: conflict-free ldmatrix)
#define IMG (128 * STRA)    // fp16 elems per 128x128 W image (34816 B)
#define NT 391              // 128-row tiles covering N_NODES
#define GRID_GEMM 148       // persistent CTAs
#define GT 512              // GEMM threads (16 warps)

// ---------------------------------------------------------------------------
// Scratch.  Features: plain fp16 rows, 64 words (256 B) each.
// ---------------------------------------------------------------------------
__device__ uint32_t g_xs[N_NODES * NW2];
__device__ uint32_t g_aggs[N_NODES * NW2];
__device__ uint32_t g_h1[N_NODES * NW2];
__device__ uint32_t g_h2[N_NODES * NW2];
__device__ float g_sums[N_GRAPHS * D];
__device__ float g_cnt[N_GRAPHS];
__device__ int g_deg[N_NODES];
__device__ int g_adj[N_NODES * SLOTS];
__device__ __align__(16) __half g_Wf16[3 * 2 * IMG];   // per layer: [rel][root]

// ---------------------------------------------------------------------------
// Helpers
// ---------------------------------------------------------------------------
__device__ __forceinline__ uint32_t smem_u32(const void* p) {
    uint32_t a;
    asm("{ .reg .u64 t; cvta.to.shared.u64 t, %1; cvt.u32.u64 %0, t; }"
        : "=r"(a) : "l"(p));
    return a;
}
__device__ __forceinline__ float2 up2(uint32_t w) {    // packed fp16x2 -> f32x2
    float2 f;
    asm("{ .reg .f16 h0, h1; mov.b32 {h0, h1}, %2;\n\t"
        "  cvt.f32.f16 %0, h0; cvt.f32.f16 %1, h1; }"
        : "=f"(f.x), "=f"(f.y) : "r"(w));
    return f;
}
__device__ __forceinline__ uint32_t packh2(float a, float b) {  // a->lo, b->hi
    uint32_t r;
    asm("cvt.rn.f16x2.f32 %0, %1, %2;" : "=r"(r) : "f"(b), "f"(a));
    return r;
}
__device__ __forceinline__ void ldsm4(uint32_t* r, uint32_t addr) {
    asm volatile("ldmatrix.sync.aligned.m8n8.x4.shared.b16 {%0,%1,%2,%3}, [%4];"
                 : "=r"(r[0]), "=r"(r[1]), "=r"(r[2]), "=r"(r[3]) : "r"(addr));
}
__device__ __forceinline__ void mma16816h(float* c, const uint32_t* a,
                                          uint32_t b0, uint32_t b1) {
    asm volatile(
        "mma.sync.aligned.m16n8k16.row.col.f32.f16.f16.f32 "
        "{%0,%1,%2,%3}, {%4,%5,%6,%7}, {%8,%9}, {%0,%1,%2,%3};"
        : "+f"(c[0]), "+f"(c[1]), "+f"(c[2]), "+f"(c[3])
        : "r"(a[0]), "r"(a[1]), "r"(a[2]), "r"(a[3]), "r"(b0), "r"(b1));
}

// ---------------------------------------------------------------------------
// Setup: zero deg/pool, convert x -> plain fp16
// ---------------------------------------------------------------------------
__global__ void k_setup(const float* __restrict__ x) {
    int i = blockIdx.x * blockDim.x + threadIdx.x;
    if (i < N_NODES) g_deg[i] = 0;
    if (i < N_GRAPHS * D) g_sums[i] = 0.f;
    if (i < N_GRAPHS) g_cnt[i] = 0.f;
    if (i < N_NODES * 32) {
        int node = i >> 5;
        int t4 = i & 31;
        float4 v = *reinterpret_cast<const float4*>(x + (size_t)node * D + t4 * 4);
        *reinterpret_cast<uint2*>(g_xs + (size_t)node * NW2 + t4 * 2) =
            make_uint2(packh2(v.x, v.y), packh2(v.z, v.w));
    }
}

__global__ void k_fill(const int* __restrict__ ei) {
    int e = blockIdx.x * blockDim.x + threadIdx.x;
    if (e < N_EDGES) {
        int dst = ei[N_EDGES + e];
        int p = atomicAdd(&g_deg[dst], 1);
        if (p < SLOTS) g_adj[dst * SLOTS + p] = ei[e];
    }
}

// W (k-major [k][n]) -> single fp16 image, transposed to [n][k], stride STRA.
__global__ __launch_bounds__(256) void k_wprep(const float* __restrict__ Wrel,
                                               const float* __restrict__ Wroot) {
    int m = blockIdx.x;                       // layer*2 + isroot
    const float* W = ((m & 1) ? Wroot : Wrel) + (m >> 1) * D * D;
    __half* dst = g_Wf16 + m * IMG;
    for (int i = threadIdx.x; i < D * D; i += 256) {
        int n = i & 127;
        int k = i >> 7;
        dst[n * STRA + k] = __float2half(W[k * D + n]);
    }
}

// ---------------------------------------------------------------------------
// Gather: aggs[n] = fp16( sum_{s in adj(n)} h[s] ).
// TWO nodes per warp: 16 lanes per node, LDG.128 per lane per neighbor.
// ---------------------------------------------------------------------------
__global__ __launch_bounds__(256) void k_gather(const uint32_t* __restrict__ h) {
    int gwarp = (blockIdx.x * blockDim.x + threadIdx.x) >> 5;
    int lane = threadIdx.x & 31;
    int n = gwarp * 2 + (lane >> 4);          // node for this half-warp
    if (n >= N_NODES) return;
    int hl = lane & 15;                       // half-lane: owns uint4 chunk hl
    int deg = g_deg[n];
    if (deg > SLOTS) deg = SLOTS;
    const int* adj = g_adj + n * SLOTS;
    float a0 = 0.f, a1 = 0.f, a2 = 0.f, a3 = 0.f;
    float a4 = 0.f, a5 = 0.f, a6 = 0.f, a7 = 0.f;
    int i = 0;
    for (; i + 4 <= deg; i += 4) {
#pragma unroll
        for (int j = 0; j < 4; j++) {
            int s = adj[i + j];
            uint4 u = *reinterpret_cast<const uint4*>(h + (size_t)s * NW2 + hl * 4);
            float2 f0 = up2(u.x), f1 = up2(u.y), f2 = up2(u.z), f3 = up2(u.w);
            a0 += f0.x; a1 += f0.y; a2 += f1.x; a3 += f1.y;
            a4 += f2.x; a5 += f2.y; a6 += f3.x; a7 += f3.y;
        }
    }
    for (; i < deg; i++) {
        int s = adj[i];
        uint4 u = *reinterpret_cast<const uint4*>(h + (size_t)s * NW2 + hl * 4);
        float2 f0 = up2(u.x), f1 = up2(u.y), f2 = up2(u.z), f3 = up2(u.w);
        a0 += f0.x; a1 += f0.y; a2 += f1.x; a3 += f1.y;
        a4 += f2.x; a5 += f2.y; a6 += f3.x; a7 += f3.y;
    }
    *reinterpret_cast<uint4*>(g_aggs + (size_t)n * NW2 + hl * 4) =
        make_uint4(packh2(a0, a1), packh2(a2, a3), packh2(a4, a5), packh2(a6, a7));
}

// ---------------------------------------------------------------------------
// Persistent HMMA GraphConv GEMM:
//   hout = fp16( relu( agg@Wrel + hin@Wroot + b ) )
// 148 CTAs x 512 thr (16 warps, warp tile 32m x 32n), loop over 391 tiles.
// Both A operands resident: one copy phase + 2 syncs per tile.
// SMEM: Wrel 34816 | Wroot 34816 | bias 512 | Aagg 34816 | Ah 34816 = 139776
// ---------------------------------------------------------------------------
#define SMB_BIAS 69632
#define SMB_AGG  70144
#define SMB_AH   104960
#define SM_TOTAL 139776

// Copy both 128-row fp16 tiles (agg + hin) into smem (stride 68 words/row).
__device__ __forceinline__ void copyAB(const uint32_t* __restrict__ agg,
                                       const uint32_t* __restrict__ hin,
                                       int row0, char* smem) {
    uint32_t* aP = reinterpret_cast<uint32_t*>(smem + SMB_AGG);
    uint32_t* hP = reinterpret_cast<uint32_t*>(smem + SMB_AH);
#pragma unroll
    for (int it = 0; it < 8; it++) {
        int idx = it * GT + threadIdx.x;
        int row = idx >> 5;
        int t2 = idx & 31;
        int grow = row0 + row;
        uint2 ua = make_uint2(0u, 0u);
        uint2 uh = make_uint2(0u, 0u);
        if (grow < N_NODES) {
            ua = *reinterpret_cast<const uint2*>(agg + (size_t)grow * NW2 + t2 * 2);
            uh = *reinterpret_cast<const uint2*>(hin + (size_t)grow * NW2 + t2 * 2);
        }
        *reinterpret_cast<uint2*>(aP + row * 68 + t2 * 2) = ua;
        *reinterpret_cast<uint2*>(hP + row * 68 + t2 * 2) = uh;
    }
}

// One K=128 pass: c += A @ W
__device__ __forceinline__ void mma_pass(float c[2][4][4], uint32_t aBase,
                                         uint32_t wBase, int mrow0, int ncol0,
                                         int lane) {
    int arow = (lane & 7) + ((lane >> 3) & 1) * 8;
    int akc = ((lane >> 4) & 1) * 8;
    int bn = (lane & 7) + ((lane >> 4) & 1) * 8;
    int bkc = ((lane >> 3) & 1) * 8;

#pragma unroll
    for (int ks = 0; ks < 8; ks++) {
        int k0 = ks * 16;
        uint32_t a[2][4];
#pragma unroll
        for (int mt = 0; mt < 2; mt++) {
            uint32_t off = (uint32_t)((mrow0 + mt * 16 + arow) * (STRA * 2) +
                                      (k0 + akc) * 2);
            ldsm4(a[mt], aBase + off);
        }
#pragma unroll
        for (int np = 0; np < 2; np++) {
            uint32_t woff = (uint32_t)((ncol0 + np * 16 + bn) * (STRA * 2) +
                                       (k0 + bkc) * 2);
            uint32_t b[4];
            ldsm4(b, wBase + woff);
#pragma unroll
            for (int mt = 0; mt < 2; mt++) {
                mma16816h(c[mt][np * 2], a[mt], b[0], b[1]);
                mma16816h(c[mt][np * 2 + 1], a[mt], b[2], b[3]);
            }
        }
    }
}

__global__ __launch_bounds__(GT, 1)
void k_gemm_mma(const uint32_t* __restrict__ hin,
                const __half* __restrict__ wlayer,   // [rel][root] images
                const float* __restrict__ bias,
                uint32_t* __restrict__ hout) {
    extern __shared__ char smem[];
    int tid = threadIdx.x;
    int w = tid >> 5;
    int lane = tid & 31;
    int mrow0 = (w & 3) * 32;        // 4 m-warps
    int ncol0 = (w >> 2) * 32;       // 4 n-warps
    uint32_t sbase = smem_u32(smem);

    // Weights once per CTA (69632 B)
    {
        const float4* s4 = reinterpret_cast<const float4*>(wlayer);
        float4* d4 = reinterpret_cast<float4*>(smem);
        for (int i = tid; i < 4352; i += GT) d4[i] = s4[i];
    }
    if (tid < 128) ((float*)(smem + SMB_BIAS))[tid] = bias[tid];
    __syncthreads();

    const float* sb = (const float*)(smem + SMB_BIAS);
    int g = lane >> 2;
    int t = lane & 3;

    for (int tile = blockIdx.x; tile < NT; tile += GRID_GEMM) {
        int row0 = tile * 128;

        copyAB(g_aggs, hin, row0, smem);
        __syncthreads();

        float c[2][4][4];
#pragma unroll
        for (int mt = 0; mt < 2; mt++)
#pragma unroll
            for (int nt = 0; nt < 4; nt++)
#pragma unroll
                for (int i = 0; i < 4; i++) c[mt][nt][i] = 0.f;

        mma_pass(c, sbase + SMB_AGG, sbase, mrow0, ncol0, lane);        // agg@Wrel
        mma_pass(c, sbase + SMB_AH, sbase + 34816u, mrow0, ncol0, lane); // hin@Wroot
        __syncthreads();   // A buffers consumed; next copy may proceed after epi

        // Epilogue: bias + relu, write plain fp16 (registers only)
#pragma unroll
        for (int mt = 0; mt < 2; mt++) {
#pragma unroll
            for (int nt = 0; nt < 4; nt++) {
                int col = ncol0 + nt * 8 + t * 2;
                float b0 = sb[col], b1 = sb[col + 1];
                int r0 = row0 + mrow0 + mt * 16 + g;
                if (r0 < N_NODES) {
                    hout[(size_t)r0 * NW2 + (col >> 1)] =
                        packh2(fmaxf(c[mt][nt][0] + b0, 0.f),
                               fmaxf(c[mt][nt][1] + b1, 0.f));
                }
                int r1 = r0 + 8;
                if (r1 < N_NODES) {
                    hout[(size_t)r1 * NW2 + (col >> 1)] =
                        packh2(fmaxf(c[mt][nt][2] + b0, 0.f),
                               fmaxf(c[mt][nt][3] + b1, 0.f));
                }
            }
        }
    }
}

// ---------------------------------------------------------------------------
// Pool (reads plain fp16) + head
// ---------------------------------------------------------------------------
#define NODES_PER_WARP 4
__global__ __launch_bounds__(256) void k_pool(const uint32_t* __restrict__ h,
                                              const int* __restrict__ batch) {
    int gwarp = (blockIdx.x * blockDim.x + threadIdx.x) >> 5;
    int lane = threadIdx.x & 31;
#pragma unroll
    for (int i = 0; i < NODES_PER_WARP; i++) {
        int n = gwarp * NODES_PER_WARP + i;
        if (n >= N_NODES) return;
        int g = batch[n];
        uint2 u = *reinterpret_cast<const uint2*>(h + (size_t)n * NW2 + lane * 2);
        float2 f0 = up2(u.x), f1 = up2(u.y);
        float* dp = g_sums + g * D + lane * 4;
        asm volatile("red.global.add.v4.f32 [%0], {%1,%2,%3,%4};"
                     :: "l"(dp), "f"(f0.x), "f"(f0.y), "f"(f1.x), "f"(f1.y)
                     : "memory");
        if (lane == 0) atomicAdd(&g_cnt[g], 1.0f);
    }
}

__global__ __launch_bounds__(128) void k_head(const float* __restrict__ W1,
                                              const float* __restrict__ b1,
                                              const float* __restrict__ W2,
                                              const float* __restrict__ b2,
                                              float* __restrict__ out) {
    __shared__ float pooled[D];
    __shared__ float t[D];
    int g = blockIdx.x;
    int tid = threadIdx.x;
    float cnt = fmaxf(g_cnt[g], 1.0f);
    pooled[tid] = g_sums[g * D + tid] / cnt;
    __syncthreads();

    float acc = b1[tid];
#pragma unroll 8
    for (int k = 0; k < D; k++) acc += pooled[k] * W1[k * D + tid];
    t[tid] = acc;
    __syncthreads();

    if (tid < OUT_DIM) {
        float o = b2[tid];
#pragma unroll 8
        for (int k = 0; k < D; k++) o += t[k] * W2[k * OUT_DIM + tid];
        out[g * OUT_DIM + tid] = o;
    }
}

// ---------------------------------------------------------------------------
// Launch sequence (graph-capturable)
// ---------------------------------------------------------------------------
extern "C" void kernel_launch(void* const* d_in, const int* in_sizes, int n_in,
                              void* d_out, int out_size) {
    const float* x = (const float*)d_in[0];
    const int* ei = (const int*)d_in[1];      // int32 (JAX x64 disabled)
    const int* batch = (const int*)d_in[2];   // int32
    const float* Wrel = (const float*)d_in[3];
    const float* brel = (const float*)d_in[4];
    const float* Wroot = (const float*)d_in[5];
    const float* W1 = (const float*)d_in[6];
    const float* b1 = (const float*)d_in[7];
    const float* W2 = (const float*)d_in[8];
    const float* b2 = (const float*)d_in[9];
    float* out = (float*)d_out;

    cudaFuncSetAttribute(k_gemm_mma, cudaFuncAttributeMaxDynamicSharedMemorySize,
                         SM_TOTAL);

    uint32_t *xs, *h1, *h2;
    __half* wfp;
    cudaGetSymbolAddress((void**)&xs, g_xs);
    cudaGetSymbolAddress((void**)&h1, g_h1);
    cudaGetSymbolAddress((void**)&h2, g_h2);
    cudaGetSymbolAddress((void**)&wfp, g_Wf16);

    const int setup_blocks = (N_NODES * 32 + 255) / 256;
    const int edge_blocks = (N_EDGES + 255) / 256;
    const int gather_blocks = (N_NODES + 15) / 16;   // 2 nodes per warp
    const int pool_blocks = (N_NODES + 8 * NODES_PER_WARP - 1) / (8 * NODES_PER_WARP);

    // Setup
    k_setup<<<setup_blocks, 256>>>(x);
    k_wprep<<<6, 256>>>(Wrel, Wroot);
    k_fill<<<edge_blocks, 256>>>(ei);

    // Layer 0: xs -> h1
    k_gather<<<gather_blocks, 256>>>(xs);
    k_gemm_mma<<<GRID_GEMM, GT, SM_TOTAL>>>(xs, wfp + 0 * 2 * IMG, brel, h1);
    // Layer 1: h1 -> h2
    k_gather<<<gather_blocks, 256>>>(h1);
    k_gemm_mma<<<GRID_GEMM, GT, SM_TOTAL>>>(h1, wfp + 1 * 2 * IMG, brel + D, h2);
    // Layer 2: h2 -> h1
    k_gather<<<gather_blocks, 256>>>(h2);
    k_gemm_mma<<<GRID_GEMM, GT, SM_TOTAL>>>(h2, wfp + 2 * 2 * IMG, brel + 2 * D, h1);

    // Pool + head
    k_pool<<<pool_blocks, 256>>>(h1, batch);
    k_head<<<N_GRAPHS, 128>>>(W1, b1, W2, b2, out);
}

// round 14
// speedup vs baseline: 2.3645x; 1.0273x over previous
#include <cuda_runtime.h>
#include <cuda_fp16.h>
#include <cstdint>

#define N_NODES 50000
#define N_EDGES 800000
#define D 128
#define NW2 64              // uint32 words per plain-fp16 row (256 B)
#define N_GRAPHS 128
#define OUT_DIM 16
#define SLOTS 64            // fixed adjacency slots per node (Poisson(16), P(>64)~1e-20)
#define STRA 136            // fp16 row stride for MMA tiles (272B: conflict-free ldmatrix)
#define IMG (128 * STRA)    // fp16 elems per 128x128 W image (34816 B)
#define NT 391              // 128-row tiles covering N_NODES
#define GRID_GEMM 148       // persistent CTAs
#define GT 512              // GEMM threads (16 warps)

// ---------------------------------------------------------------------------
// Scratch.  Features: plain fp16 rows, 64 words (256 B) each.
// ---------------------------------------------------------------------------
__device__ uint32_t g_xs[N_NODES * NW2];
__device__ uint32_t g_aggs[N_NODES * NW2];
__device__ uint32_t g_h1[N_NODES * NW2];
__device__ uint32_t g_h2[N_NODES * NW2];
__device__ float g_sums[N_GRAPHS * D];
__device__ float g_cnt[N_GRAPHS];
__device__ int g_deg[N_NODES];
__device__ int g_adj[N_NODES * SLOTS];
__device__ __align__(16) __half g_Wf16[3 * 2 * IMG];   // per layer: [rel][root]

// ---------------------------------------------------------------------------
// Helpers
// ---------------------------------------------------------------------------
__device__ __forceinline__ uint32_t smem_u32(const void* p) {
    uint32_t a;
    asm("{ .reg .u64 t; cvta.to.shared.u64 t, %1; cvt.u32.u64 %0, t; }"
        : "=r"(a) : "l"(p));
    return a;
}
__device__ __forceinline__ float2 up2(uint32_t w) {    // packed fp16x2 -> f32x2
    float2 f;
    asm("{ .reg .f16 h0, h1; mov.b32 {h0, h1}, %2;\n\t"
        "  cvt.f32.f16 %0, h0; cvt.f32.f16 %1, h1; }"
        : "=f"(f.x), "=f"(f.y) : "r"(w));
    return f;
}
__device__ __forceinline__ uint32_t packh2(float a, float b) {  // a->lo, b->hi
    uint32_t r;
    asm("cvt.rn.f16x2.f32 %0, %1, %2;" : "=r"(r) : "f"(b), "f"(a));
    return r;
}
__device__ __forceinline__ void ldsm4(uint32_t* r, uint32_t addr) {
    asm volatile("ldmatrix.sync.aligned.m8n8.x4.shared.b16 {%0,%1,%2,%3}, [%4];"
                 : "=r"(r[0]), "=r"(r[1]), "=r"(r[2]), "=r"(r[3]) : "r"(addr));
}
__device__ __forceinline__ void mma16816h(float* c, const uint32_t* a,
                                          uint32_t b0, uint32_t b1) {
    asm volatile(
        "mma.sync.aligned.m16n8k16.row.col.f32.f16.f16.f32 "
        "{%0,%1,%2,%3}, {%4,%5,%6,%7}, {%8,%9}, {%0,%1,%2,%3};"
        : "+f"(c[0]), "+f"(c[1]), "+f"(c[2]), "+f"(c[3])
        : "r"(a[0]), "r"(a[1]), "r"(a[2]), "r"(a[3]), "r"(b0), "r"(b1));
}

// ---------------------------------------------------------------------------
// Setup: zero deg/pool, convert x -> plain fp16
// ---------------------------------------------------------------------------
__global__ void k_setup(const float* __restrict__ x) {
    int i = blockIdx.x * blockDim.x + threadIdx.x;
    if (i < N_NODES) g_deg[i] = 0;
    if (i < N_GRAPHS * D) g_sums[i] = 0.f;
    if (i < N_GRAPHS) g_cnt[i] = 0.f;
    if (i < N_NODES * 32) {
        int node = i >> 5;
        int t4 = i & 31;
        float4 v = *reinterpret_cast<const float4*>(x + (size_t)node * D + t4 * 4);
        *reinterpret_cast<uint2*>(g_xs + (size_t)node * NW2 + t4 * 2) =
            make_uint2(packh2(v.x, v.y), packh2(v.z, v.w));
    }
}

__global__ void k_fill(const int* __restrict__ ei) {
    int e = blockIdx.x * blockDim.x + threadIdx.x;
    if (e < N_EDGES) {
        int dst = ei[N_EDGES + e];
        int p = atomicAdd(&g_deg[dst], 1);
        if (p < SLOTS) g_adj[dst * SLOTS + p] = ei[e];
    }
}

// W (k-major [k][n]) -> single fp16 image, transposed to [n][k], stride STRA.
__global__ __launch_bounds__(256) void k_wprep(const float* __restrict__ Wrel,
                                               const float* __restrict__ Wroot) {
    int m = blockIdx.x;                       // layer*2 + isroot
    const float* W = ((m & 1) ? Wroot : Wrel) + (m >> 1) * D * D;
    __half* dst = g_Wf16 + m * IMG;
    for (int i = threadIdx.x; i < D * D; i += 256) {
        int n = i & 127;
        int k = i >> 7;
        dst[n * STRA + k] = __float2half(W[k * D + n]);
    }
}

// ---------------------------------------------------------------------------
// Gather: aggs[n] = fp16( sum_{s in adj(n)} h[s] ).
// TWO nodes per warp: 16 lanes per node, LDG.128 per lane per neighbor.
// ---------------------------------------------------------------------------
__global__ __launch_bounds__(256) void k_gather(const uint32_t* __restrict__ h) {
    int gwarp = (blockIdx.x * blockDim.x + threadIdx.x) >> 5;
    int lane = threadIdx.x & 31;
    int n = gwarp * 2 + (lane >> 4);          // node for this half-warp
    if (n >= N_NODES) return;
    int hl = lane & 15;                       // half-lane: owns uint4 chunk hl
    int deg = g_deg[n];
    if (deg > SLOTS) deg = SLOTS;
    const int* adj = g_adj + n * SLOTS;
    float a0 = 0.f, a1 = 0.f, a2 = 0.f, a3 = 0.f;
    float a4 = 0.f, a5 = 0.f, a6 = 0.f, a7 = 0.f;
    int i = 0;
    for (; i + 4 <= deg; i += 4) {
#pragma unroll
        for (int j = 0; j < 4; j++) {
            int s = adj[i + j];
            uint4 u = *reinterpret_cast<const uint4*>(h + (size_t)s * NW2 + hl * 4);
            float2 f0 = up2(u.x), f1 = up2(u.y), f2 = up2(u.z), f3 = up2(u.w);
            a0 += f0.x; a1 += f0.y; a2 += f1.x; a3 += f1.y;
            a4 += f2.x; a5 += f2.y; a6 += f3.x; a7 += f3.y;
        }
    }
    for (; i < deg; i++) {
        int s = adj[i];
        uint4 u = *reinterpret_cast<const uint4*>(h + (size_t)s * NW2 + hl * 4);
        float2 f0 = up2(u.x), f1 = up2(u.y), f2 = up2(u.z), f3 = up2(u.w);
        a0 += f0.x; a1 += f0.y; a2 += f1.x; a3 += f1.y;
        a4 += f2.x; a5 += f2.y; a6 += f3.x; a7 += f3.y;
    }
    *reinterpret_cast<uint4*>(g_aggs + (size_t)n * NW2 + hl * 4) =
        make_uint4(packh2(a0, a1), packh2(a2, a3), packh2(a4, a5), packh2(a6, a7));
}

// ---------------------------------------------------------------------------
// Persistent HMMA GraphConv GEMM, double-buffered software pipeline:
//   hout = fp16( relu( agg@Wrel + hin@Wroot + b ) )
// 148 CTAs x 512 thr (16 warps, warp tile 32m x 32n), loop over 391 tiles.
// SMEM: Wrel 34816 | Wroot 34816 | bias 512 | buf0 {agg,h} 69632 | buf1 69632
// ---------------------------------------------------------------------------
#define SMB_BIAS 69632
#define SMB_BUF0 70144
#define SMB_BUF1 139776
#define SM_TOTAL 209408

// Load one 128-row tile pair (agg + hin) into registers (4 x uint4 each).
__device__ __forceinline__ void ldTile(const uint32_t* __restrict__ agg,
                                       const uint32_t* __restrict__ hin,
                                       int row0, uint4* ra, uint4* rh) {
#pragma unroll
    for (int it = 0; it < 4; it++) {
        int idx = it * GT + threadIdx.x;
        int row = idx >> 4;                  // 16 uint4 per row
        int t4 = idx & 15;
        int grow = row0 + row;
        uint4 ua = make_uint4(0u, 0u, 0u, 0u);
        uint4 uh = make_uint4(0u, 0u, 0u, 0u);
        if (grow < N_NODES) {
            ua = *reinterpret_cast<const uint4*>(agg + (size_t)grow * NW2 + t4 * 4);
            uh = *reinterpret_cast<const uint4*>(hin + (size_t)grow * NW2 + t4 * 4);
        }
        ra[it] = ua;
        rh[it] = uh;
    }
}

// Store prefetched registers into an smem buffer (stride 68 words/row).
__device__ __forceinline__ void stTile(char* smem, uint32_t bufOff,
                                       const uint4* ra, const uint4* rh) {
    uint32_t* aP = reinterpret_cast<uint32_t*>(smem + bufOff);
    uint32_t* hP = reinterpret_cast<uint32_t*>(smem + bufOff + 34816);
#pragma unroll
    for (int it = 0; it < 4; it++) {
        int idx = it * GT + threadIdx.x;
        int row = idx >> 4;
        int t4 = idx & 15;
        *reinterpret_cast<uint4*>(aP + row * 68 + t4 * 4) = ra[it];
        *reinterpret_cast<uint4*>(hP + row * 68 + t4 * 4) = rh[it];
    }
}

// One K=128 pass: c += A @ W
__device__ __forceinline__ void mma_pass(float c[2][4][4], uint32_t aBase,
                                         uint32_t wBase, int mrow0, int ncol0,
                                         int lane) {
    int arow = (lane & 7) + ((lane >> 3) & 1) * 8;
    int akc = ((lane >> 4) & 1) * 8;
    int bn = (lane & 7) + ((lane >> 4) & 1) * 8;
    int bkc = ((lane >> 3) & 1) * 8;

#pragma unroll
    for (int ks = 0; ks < 8; ks++) {
        int k0 = ks * 16;
        uint32_t a[2][4];
#pragma unroll
        for (int mt = 0; mt < 2; mt++) {
            uint32_t off = (uint32_t)((mrow0 + mt * 16 + arow) * (STRA * 2) +
                                      (k0 + akc) * 2);
            ldsm4(a[mt], aBase + off);
        }
#pragma unroll
        for (int np = 0; np < 2; np++) {
            uint32_t woff = (uint32_t)((ncol0 + np * 16 + bn) * (STRA * 2) +
                                       (k0 + bkc) * 2);
            uint32_t b[4];
            ldsm4(b, wBase + woff);
#pragma unroll
            for (int mt = 0; mt < 2; mt++) {
                mma16816h(c[mt][np * 2], a[mt], b[0], b[1]);
                mma16816h(c[mt][np * 2 + 1], a[mt], b[2], b[3]);
            }
        }
    }
}

__global__ __launch_bounds__(GT, 1)
void k_gemm_mma(const uint32_t* __restrict__ hin,
                const __half* __restrict__ wlayer,   // [rel][root] images
                const float* __restrict__ bias,
                uint32_t* __restrict__ hout) {
    extern __shared__ char smem[];
    int tid = threadIdx.x;
    int w = tid >> 5;
    int lane = tid & 31;
    int mrow0 = (w & 3) * 32;        // 4 m-warps
    int ncol0 = (w >> 2) * 32;       // 4 n-warps
    uint32_t sbase = smem_u32(smem);

    // Weights once per CTA (69632 B)
    {
        const float4* s4 = reinterpret_cast<const float4*>(wlayer);
        float4* d4 = reinterpret_cast<float4*>(smem);
        for (int i = tid; i < 4352; i += GT) d4[i] = s4[i];
    }
    if (tid < 128) ((float*)(smem + SMB_BIAS))[tid] = bias[tid];

    const float* sb = (const float*)(smem + SMB_BIAS);
    int g = lane >> 2;
    int t = lane & 3;

    uint4 ra[4], rh[4];
    const uint32_t bufOff[2] = {SMB_BUF0, SMB_BUF1};

    // Prologue: fill buf0 with this CTA's first tile
    int tile = blockIdx.x;
    ldTile(g_aggs, hin, tile * 128, ra, rh);
    stTile(smem, SMB_BUF0, ra, rh);
    __syncthreads();

    int cur = 0;
    while (tile < NT) {
        int next = tile + GRID_GEMM;
        // Prefetch next tile into registers (LDGs overlap the MMAs below)
        if (next < NT) ldTile(g_aggs, hin, next * 128, ra, rh);

        float c[2][4][4];
#pragma unroll
        for (int mt = 0; mt < 2; mt++)
#pragma unroll
            for (int nt = 0; nt < 4; nt++)
#pragma unroll
                for (int i = 0; i < 4; i++) c[mt][nt][i] = 0.f;

        mma_pass(c, sbase + bufOff[cur], sbase, mrow0, ncol0, lane);          // agg@Wrel
        mma_pass(c, sbase + bufOff[cur] + 34816u, sbase + 34816u, mrow0, ncol0,
                 lane);                                                        // hin@Wroot

        if (next < NT) stTile(smem, bufOff[cur ^ 1], ra, rh);
        __syncthreads();

        // Epilogue: bias + relu, write plain fp16 (registers + global only)
        int row0 = tile * 128;
#pragma unroll
        for (int mt = 0; mt < 2; mt++) {
#pragma unroll
            for (int nt = 0; nt < 4; nt++) {
                int col = ncol0 + nt * 8 + t * 2;
                float b0 = sb[col], b1 = sb[col + 1];
                int r0 = row0 + mrow0 + mt * 16 + g;
                if (r0 < N_NODES) {
                    hout[(size_t)r0 * NW2 + (col >> 1)] =
                        packh2(fmaxf(c[mt][nt][0] + b0, 0.f),
                               fmaxf(c[mt][nt][1] + b1, 0.f));
                }
                int r1 = r0 + 8;
                if (r1 < N_NODES) {
                    hout[(size_t)r1 * NW2 + (col >> 1)] =
                        packh2(fmaxf(c[mt][nt][2] + b0, 0.f),
                               fmaxf(c[mt][nt][3] + b1, 0.f));
                }
            }
        }
        tile = next;
        cur ^= 1;
    }
}

// ---------------------------------------------------------------------------
// Pool (reads plain fp16) + head
// ---------------------------------------------------------------------------
#define NODES_PER_WARP 4
__global__ __launch_bounds__(256) void k_pool(const uint32_t* __restrict__ h,
                                              const int* __restrict__ batch) {
    int gwarp = (blockIdx.x * blockDim.x + threadIdx.x) >> 5;
    int lane = threadIdx.x & 31;
#pragma unroll
    for (int i = 0; i < NODES_PER_WARP; i++) {
        int n = gwarp * NODES_PER_WARP + i;
        if (n >= N_NODES) return;
        int g = batch[n];
        uint2 u = *reinterpret_cast<const uint2*>(h + (size_t)n * NW2 + lane * 2);
        float2 f0 = up2(u.x), f1 = up2(u.y);
        float* dp = g_sums + g * D + lane * 4;
        asm volatile("red.global.add.v4.f32 [%0], {%1,%2,%3,%4};"
                     :: "l"(dp), "f"(f0.x), "f"(f0.y), "f"(f1.x), "f"(f1.y)
                     : "memory");
        if (lane == 0) atomicAdd(&g_cnt[g], 1.0f);
    }
}

__global__ __launch_bounds__(128) void k_head(const float* __restrict__ W1,
                                              const float* __restrict__ b1,
                                              const float* __restrict__ W2,
                                              const float* __restrict__ b2,
                                              float* __restrict__ out) {
    __shared__ float pooled[D];
    __shared__ float t[D];
    int g = blockIdx.x;
    int tid = threadIdx.x;
    float cnt = fmaxf(g_cnt[g], 1.0f);
    pooled[tid] = g_sums[g * D + tid] / cnt;
    __syncthreads();

    float acc = b1[tid];
#pragma unroll 8
    for (int k = 0; k < D; k++) acc += pooled[k] * W1[k * D + tid];
    t[tid] = acc;
    __syncthreads();

    if (tid < OUT_DIM) {
        float o = b2[tid];
#pragma unroll 8
        for (int k = 0; k < D; k++) o += t[k] * W2[k * OUT_DIM + tid];
        out[g * OUT_DIM + tid] = o;
    }
}

// ---------------------------------------------------------------------------
// Launch sequence (graph-capturable)
// ---------------------------------------------------------------------------
extern "C" void kernel_launch(void* const* d_in, const int* in_sizes, int n_in,
                              void* d_out, int out_size) {
    const float* x = (const float*)d_in[0];
    const int* ei = (const int*)d_in[1];      // int32 (JAX x64 disabled)
    const int* batch = (const int*)d_in[2];   // int32
    const float* Wrel = (const float*)d_in[3];
    const float* brel = (const float*)d_in[4];
    const float* Wroot = (const float*)d_in[5];
    const float* W1 = (const float*)d_in[6];
    const float* b1 = (const float*)d_in[7];
    const float* W2 = (const float*)d_in[8];
    const float* b2 = (const float*)d_in[9];
    float* out = (float*)d_out;

    cudaFuncSetAttribute(k_gemm_mma, cudaFuncAttributeMaxDynamicSharedMemorySize,
                         SM_TOTAL);

    uint32_t *xs, *h1, *h2;
    __half* wfp;
    cudaGetSymbolAddress((void**)&xs, g_xs);
    cudaGetSymbolAddress((void**)&h1, g_h1);
    cudaGetSymbolAddress((void**)&h2, g_h2);
    cudaGetSymbolAddress((void**)&wfp, g_Wf16);

    const int setup_blocks = (N_NODES * 32 + 255) / 256;
    const int edge_blocks = (N_EDGES + 255) / 256;
    const int gather_blocks = (N_NODES + 15) / 16;   // 2 nodes per warp
    const int pool_blocks = (N_NODES + 8 * NODES_PER_WARP - 1) / (8 * NODES_PER_WARP);

    // Setup
    k_setup<<<setup_blocks, 256>>>(x);
    k_wprep<<<6, 256>>>(Wrel, Wroot);
    k_fill<<<edge_blocks, 256>>>(ei);

    // Layer 0: xs -> h1
    k_gather<<<gather_blocks, 256>>>(xs);
    k_gemm_mma<<<GRID_GEMM, GT, SM_TOTAL>>>(xs, wfp + 0 * 2 * IMG, brel, h1);
    // Layer 1: h1 -> h2
    k_gather<<<gather_blocks, 256>>>(h1);
    k_gemm_mma<<<GRID_GEMM, GT, SM_TOTAL>>>(h1, wfp + 1 * 2 * IMG, brel + D, h2);
    // Layer 2: h2 -> h1
    k_gather<<<gather_blocks, 256>>>(h2);
    k_gemm_mma<<<GRID_GEMM, GT, SM_TOTAL>>>(h2, wfp + 2 * 2 * IMG, brel + 2 * D, h1);

    // Pool + head
    k_pool<<<pool_blocks, 256>>>(h1, batch);
    k_head<<<N_GRAPHS, 128>>>(W1, b1, W2, b2, out);
}

// round 15
// speedup vs baseline: 2.4343x; 1.0295x over previous
#include <cuda_runtime.h>
#include <cuda_fp16.h>
#include <cstdint>

#define N_NODES 50000
#define N_EDGES 800000
#define D 128
#define NW2 64              // uint32 words per plain-fp16 row (256 B)
#define N_GRAPHS 128
#define OUT_DIM 16
#define SLOTS 64            // fixed adjacency slots per node (Poisson(16), P(>64)~1e-20)
#define STRA 136            // fp16 row stride for MMA tiles (272B: conflict-free ldmatrix)
#define IMG (128 * STRA)    // fp16 elems per 128x128 W image (34816 B)
#define NT 391              // 128-row tiles covering N_NODES
#define GRID_GEMM 148       // persistent CTAs
#define GT 512              // GEMM threads (16 warps)

// ---------------------------------------------------------------------------
// Scratch.  Features: plain fp16 rows, 64 words (256 B) each.
// ---------------------------------------------------------------------------
__device__ uint32_t g_xs[N_NODES * NW2];
__device__ uint32_t g_aggs[N_NODES * NW2];
__device__ uint32_t g_h1[N_NODES * NW2];
__device__ uint32_t g_h2[N_NODES * NW2];
__device__ float g_sums[N_GRAPHS * D];
__device__ float g_cnt[N_GRAPHS];
__device__ int g_deg[N_NODES];
__device__ int g_adj[N_NODES * SLOTS];
__device__ __align__(16) __half g_Wf16[3 * 2 * IMG];   // per layer: [rel][root]

// ---------------------------------------------------------------------------
// Helpers
// ---------------------------------------------------------------------------
__device__ __forceinline__ uint32_t smem_u32(const void* p) {
    uint32_t a;
    asm("{ .reg .u64 t; cvta.to.shared.u64 t, %1; cvt.u32.u64 %0, t; }"
        : "=r"(a) : "l"(p));
    return a;
}
__device__ __forceinline__ float2 up2(uint32_t w) {    // packed fp16x2 -> f32x2
    float2 f;
    asm("{ .reg .f16 h0, h1; mov.b32 {h0, h1}, %2;\n\t"
        "  cvt.f32.f16 %0, h0; cvt.f32.f16 %1, h1; }"
        : "=f"(f.x), "=f"(f.y) : "r"(w));
    return f;
}
__device__ __forceinline__ uint32_t packh2(float a, float b) {  // a->lo, b->hi
    uint32_t r;
    asm("cvt.rn.f16x2.f32 %0, %1, %2;" : "=r"(r) : "f"(b), "f"(a));
    return r;
}
__device__ __forceinline__ uint32_t hadd2(uint32_t a, uint32_t b) {
    uint32_t r;
    asm("add.rn.f16x2 %0, %1, %2;" : "=r"(r) : "r"(a), "r"(b));
    return r;
}
__device__ __forceinline__ void ldsm4(uint32_t* r, uint32_t addr) {
    asm volatile("ldmatrix.sync.aligned.m8n8.x4.shared.b16 {%0,%1,%2,%3}, [%4];"
                 : "=r"(r[0]), "=r"(r[1]), "=r"(r[2]), "=r"(r[3]) : "r"(addr));
}
__device__ __forceinline__ void mma16816h(float* c, const uint32_t* a,
                                          uint32_t b0, uint32_t b1) {
    asm volatile(
        "mma.sync.aligned.m16n8k16.row.col.f32.f16.f16.f32 "
        "{%0,%1,%2,%3}, {%4,%5,%6,%7}, {%8,%9}, {%0,%1,%2,%3};"
        : "+f"(c[0]), "+f"(c[1]), "+f"(c[2]), "+f"(c[3])
        : "r"(a[0]), "r"(a[1]), "r"(a[2]), "r"(a[3]), "r"(b0), "r"(b1));
}

// ---------------------------------------------------------------------------
// Setup: zero deg/pool, convert x -> plain fp16, transpose weights to fp16.
// Extra 6 blocks (past SETUP_BLOCKS) do the weight prep.
// ---------------------------------------------------------------------------
#define SETUP_BLOCKS 6250    // ceil(N_NODES*32 / 256)
__global__ void k_setup(const float* __restrict__ x,
                        const float* __restrict__ Wrel,
                        const float* __restrict__ Wroot) {
    if (blockIdx.x >= SETUP_BLOCKS) {
        int m = blockIdx.x - SETUP_BLOCKS;    // layer*2 + isroot
        const float* W = ((m & 1) ? Wroot : Wrel) + (m >> 1) * D * D;
        __half* dst = g_Wf16 + m * IMG;
        for (int i = threadIdx.x; i < D * D; i += 256) {
            int n = i & 127;
            int k = i >> 7;
            dst[n * STRA + k] = __float2half(W[k * D + n]);
        }
        return;
    }
    int i = blockIdx.x * blockDim.x + threadIdx.x;
    if (i < N_NODES) g_deg[i] = 0;
    if (i < N_GRAPHS * D) g_sums[i] = 0.f;
    if (i < N_GRAPHS) g_cnt[i] = 0.f;
    if (i < N_NODES * 32) {
        int node = i >> 5;
        int t4 = i & 31;
        float4 v = *reinterpret_cast<const float4*>(x + (size_t)node * D + t4 * 4);
        *reinterpret_cast<uint2*>(g_xs + (size_t)node * NW2 + t4 * 2) =
            make_uint2(packh2(v.x, v.y), packh2(v.z, v.w));
    }
}

__global__ void k_fill(const int* __restrict__ ei) {
    int e = blockIdx.x * blockDim.x + threadIdx.x;
    if (e < N_EDGES) {
        int dst = ei[N_EDGES + e];
        int p = atomicAdd(&g_deg[dst], 1);
        if (p < SLOTS) g_adj[dst * SLOTS + p] = ei[e];
    }
}

// ---------------------------------------------------------------------------
// Gather: aggs[n] = fp16( sum_{s in adj(n)} h[s] ).
// TWO nodes per warp, 16 lanes/node, LDG.128 per lane per neighbor.
// One-level fp16 pair-summing (HADD2) before f32 accumulate: ~1.55x fewer
// non-LDG instructions; adds ~1.7e-4 relative error (same-sign averaging).
// ---------------------------------------------------------------------------
__global__ __launch_bounds__(256) void k_gather(const uint32_t* __restrict__ h) {
    int gwarp = (blockIdx.x * blockDim.x + threadIdx.x) >> 5;
    int lane = threadIdx.x & 31;
    int n = gwarp * 2 + (lane >> 4);          // node for this half-warp
    if (n >= N_NODES) return;
    int hl = lane & 15;                       // half-lane: owns uint4 chunk hl
    int deg = g_deg[n];
    if (deg > SLOTS) deg = SLOTS;
    const int* adj = g_adj + n * SLOTS;
    float a0 = 0.f, a1 = 0.f, a2 = 0.f, a3 = 0.f;
    float a4 = 0.f, a5 = 0.f, a6 = 0.f, a7 = 0.f;

#define ACC_U4(u) do { \
        float2 f0 = up2((u).x), f1 = up2((u).y), f2 = up2((u).z), f3 = up2((u).w); \
        a0 += f0.x; a1 += f0.y; a2 += f1.x; a3 += f1.y; \
        a4 += f2.x; a5 += f2.y; a6 += f3.x; a7 += f3.y; } while (0)

    int i = 0;
    for (; i + 4 <= deg; i += 4) {
        int s0 = adj[i], s1 = adj[i + 1], s2 = adj[i + 2], s3 = adj[i + 3];
        uint4 u0 = *reinterpret_cast<const uint4*>(h + (size_t)s0 * NW2 + hl * 4);
        uint4 u1 = *reinterpret_cast<const uint4*>(h + (size_t)s1 * NW2 + hl * 4);
        uint4 u2 = *reinterpret_cast<const uint4*>(h + (size_t)s2 * NW2 + hl * 4);
        uint4 u3 = *reinterpret_cast<const uint4*>(h + (size_t)s3 * NW2 + hl * 4);
        uint4 p = make_uint4(hadd2(u0.x, u1.x), hadd2(u0.y, u1.y),
                             hadd2(u0.z, u1.z), hadd2(u0.w, u1.w));
        uint4 q = make_uint4(hadd2(u2.x, u3.x), hadd2(u2.y, u3.y),
                             hadd2(u2.z, u3.z), hadd2(u2.w, u3.w));
        ACC_U4(p);
        ACC_U4(q);
    }
    if (i + 2 <= deg) {
        int s0 = adj[i], s1 = adj[i + 1];
        uint4 u0 = *reinterpret_cast<const uint4*>(h + (size_t)s0 * NW2 + hl * 4);
        uint4 u1 = *reinterpret_cast<const uint4*>(h + (size_t)s1 * NW2 + hl * 4);
        uint4 p = make_uint4(hadd2(u0.x, u1.x), hadd2(u0.y, u1.y),
                             hadd2(u0.z, u1.z), hadd2(u0.w, u1.w));
        ACC_U4(p);
        i += 2;
    }
    if (i < deg) {
        int s = adj[i];
        uint4 u = *reinterpret_cast<const uint4*>(h + (size_t)s * NW2 + hl * 4);
        ACC_U4(u);
    }
#undef ACC_U4

    *reinterpret_cast<uint4*>(g_aggs + (size_t)n * NW2 + hl * 4) =
        make_uint4(packh2(a0, a1), packh2(a2, a3), packh2(a4, a5), packh2(a6, a7));
}

// ---------------------------------------------------------------------------
// Persistent HMMA GraphConv GEMM, double-buffered software pipeline:
//   hout = fp16( relu( agg@Wrel + hin@Wroot + b ) )
// 148 CTAs x 512 thr (16 warps, warp tile 32m x 32n), loop over 391 tiles.
// SMEM: Wrel 34816 | Wroot 34816 | bias 512 | buf0 {agg,h} 69632 | buf1 69632
// ---------------------------------------------------------------------------
#define SMB_BIAS 69632
#define SMB_BUF0 70144
#define SMB_BUF1 139776
#define SM_TOTAL 209408

// Load one 128-row tile pair (agg + hin) into registers (4 x uint4 each).
__device__ __forceinline__ void ldTile(const uint32_t* __restrict__ agg,
                                       const uint32_t* __restrict__ hin,
                                       int row0, uint4* ra, uint4* rh) {
#pragma unroll
    for (int it = 0; it < 4; it++) {
        int idx = it * GT + threadIdx.x;
        int row = idx >> 4;                  // 16 uint4 per row
        int t4 = idx & 15;
        int grow = row0 + row;
        uint4 ua = make_uint4(0u, 0u, 0u, 0u);
        uint4 uh = make_uint4(0u, 0u, 0u, 0u);
        if (grow < N_NODES) {
            ua = *reinterpret_cast<const uint4*>(agg + (size_t)grow * NW2 + t4 * 4);
            uh = *reinterpret_cast<const uint4*>(hin + (size_t)grow * NW2 + t4 * 4);
        }
        ra[it] = ua;
        rh[it] = uh;
    }
}

// Store prefetched registers into an smem buffer (stride 68 words/row).
__device__ __forceinline__ void stTile(char* smem, uint32_t bufOff,
                                       const uint4* ra, const uint4* rh) {
    uint32_t* aP = reinterpret_cast<uint32_t*>(smem + bufOff);
    uint32_t* hP = reinterpret_cast<uint32_t*>(smem + bufOff + 34816);
#pragma unroll
    for (int it = 0; it < 4; it++) {
        int idx = it * GT + threadIdx.x;
        int row = idx >> 4;
        int t4 = idx & 15;
        *reinterpret_cast<uint4*>(aP + row * 68 + t4 * 4) = ra[it];
        *reinterpret_cast<uint4*>(hP + row * 68 + t4 * 4) = rh[it];
    }
}

// One K=128 pass: c += A @ W
__device__ __forceinline__ void mma_pass(float c[2][4][4], uint32_t aBase,
                                         uint32_t wBase, int mrow0, int ncol0,
                                         int lane) {
    int arow = (lane & 7) + ((lane >> 3) & 1) * 8;
    int akc = ((lane >> 4) & 1) * 8;
    int bn = (lane & 7) + ((lane >> 4) & 1) * 8;
    int bkc = ((lane >> 3) & 1) * 8;

#pragma unroll
    for (int ks = 0; ks < 8; ks++) {
        int k0 = ks * 16;
        uint32_t a[2][4];
#pragma unroll
        for (int mt = 0; mt < 2; mt++) {
            uint32_t off = (uint32_t)((mrow0 + mt * 16 + arow) * (STRA * 2) +
                                      (k0 + akc) * 2);
            ldsm4(a[mt], aBase + off);
        }
#pragma unroll
        for (int np = 0; np < 2; np++) {
            uint32_t woff = (uint32_t)((ncol0 + np * 16 + bn) * (STRA * 2) +
                                       (k0 + bkc) * 2);
            uint32_t b[4];
            ldsm4(b, wBase + woff);
#pragma unroll
            for (int mt = 0; mt < 2; mt++) {
                mma16816h(c[mt][np * 2], a[mt], b[0], b[1]);
                mma16816h(c[mt][np * 2 + 1], a[mt], b[2], b[3]);
            }
        }
    }
}

__global__ __launch_bounds__(GT, 1)
void k_gemm_mma(const uint32_t* __restrict__ hin,
                const __half* __restrict__ wlayer,   // [rel][root] images
                const float* __restrict__ bias,
                uint32_t* __restrict__ hout) {
    extern __shared__ char smem[];
    int tid = threadIdx.x;
    int w = tid >> 5;
    int lane = tid & 31;
    int mrow0 = (w & 3) * 32;        // 4 m-warps
    int ncol0 = (w >> 2) * 32;       // 4 n-warps
    uint32_t sbase = smem_u32(smem);

    // Weights once per CTA (69632 B)
    {
        const float4* s4 = reinterpret_cast<const float4*>(wlayer);
        float4* d4 = reinterpret_cast<float4*>(smem);
        for (int i = tid; i < 4352; i += GT) d4[i] = s4[i];
    }
    if (tid < 128) ((float*)(smem + SMB_BIAS))[tid] = bias[tid];

    const float* sb = (const float*)(smem + SMB_BIAS);
    int g = lane >> 2;
    int t = lane & 3;

    uint4 ra[4], rh[4];
    const uint32_t bufOff[2] = {SMB_BUF0, SMB_BUF1};

    // Prologue: fill buf0 with this CTA's first tile
    int tile = blockIdx.x;
    ldTile(g_aggs, hin, tile * 128, ra, rh);
    stTile(smem, SMB_BUF0, ra, rh);
    __syncthreads();

    int cur = 0;
    while (tile < NT) {
        int next = tile + GRID_GEMM;
        // Prefetch next tile into registers (LDGs overlap the MMAs below)
        if (next < NT) ldTile(g_aggs, hin, next * 128, ra, rh);

        float c[2][4][4];
#pragma unroll
        for (int mt = 0; mt < 2; mt++)
#pragma unroll
            for (int nt = 0; nt < 4; nt++)
#pragma unroll
                for (int i = 0; i < 4; i++) c[mt][nt][i] = 0.f;

        mma_pass(c, sbase + bufOff[cur], sbase, mrow0, ncol0, lane);          // agg@Wrel
        mma_pass(c, sbase + bufOff[cur] + 34816u, sbase + 34816u, mrow0, ncol0,
                 lane);                                                        // hin@Wroot

        if (next < NT) stTile(smem, bufOff[cur ^ 1], ra, rh);
        __syncthreads();

        // Epilogue: bias + relu, write plain fp16 (registers + global only)
        int row0 = tile * 128;
#pragma unroll
        for (int mt = 0; mt < 2; mt++) {
#pragma unroll
            for (int nt = 0; nt < 4; nt++) {
                int col = ncol0 + nt * 8 + t * 2;
                float b0 = sb[col], b1 = sb[col + 1];
                int r0 = row0 + mrow0 + mt * 16 + g;
                if (r0 < N_NODES) {
                    hout[(size_t)r0 * NW2 + (col >> 1)] =
                        packh2(fmaxf(c[mt][nt][0] + b0, 0.f),
                               fmaxf(c[mt][nt][1] + b1, 0.f));
                }
                int r1 = r0 + 8;
                if (r1 < N_NODES) {
                    hout[(size_t)r1 * NW2 + (col >> 1)] =
                        packh2(fmaxf(c[mt][nt][2] + b0, 0.f),
                               fmaxf(c[mt][nt][3] + b1, 0.f));
                }
            }
        }
        tile = next;
        cur ^= 1;
    }
}

// ---------------------------------------------------------------------------
// Pool (reads plain fp16) + head
// ---------------------------------------------------------------------------
#define NODES_PER_WARP 4
__global__ __launch_bounds__(256) void k_pool(const uint32_t* __restrict__ h,
                                              const int* __restrict__ batch) {
    int gwarp = (blockIdx.x * blockDim.x + threadIdx.x) >> 5;
    int lane = threadIdx.x & 31;
#pragma unroll
    for (int i = 0; i < NODES_PER_WARP; i++) {
        int n = gwarp * NODES_PER_WARP + i;
        if (n >= N_NODES) return;
        int g = batch[n];
        uint2 u = *reinterpret_cast<const uint2*>(h + (size_t)n * NW2 + lane * 2);
        float2 f0 = up2(u.x), f1 = up2(u.y);
        float* dp = g_sums + g * D + lane * 4;
        asm volatile("red.global.add.v4.f32 [%0], {%1,%2,%3,%4};"
                     :: "l"(dp), "f"(f0.x), "f"(f0.y), "f"(f1.x), "f"(f1.y)
                     : "memory");
        if (lane == 0) atomicAdd(&g_cnt[g], 1.0f);
    }
}

__global__ __launch_bounds__(128) void k_head(const float* __restrict__ W1,
                                              const float* __restrict__ b1,
                                              const float* __restrict__ W2,
                                              const float* __restrict__ b2,
                                              float* __restrict__ out) {
    __shared__ float pooled[D];
    __shared__ float t[D];
    int g = blockIdx.x;
    int tid = threadIdx.x;
    float cnt = fmaxf(g_cnt[g], 1.0f);
    pooled[tid] = g_sums[g * D + tid] / cnt;
    __syncthreads();

    float acc = b1[tid];
#pragma unroll 8
    for (int k = 0; k < D; k++) acc += pooled[k] * W1[k * D + tid];
    t[tid] = acc;
    __syncthreads();

    if (tid < OUT_DIM) {
        float o = b2[tid];
#pragma unroll 8
        for (int k = 0; k < D; k++) o += t[k] * W2[k * OUT_DIM + tid];
        out[g * OUT_DIM + tid] = o;
    }
}

// ---------------------------------------------------------------------------
// Launch sequence (graph-capturable)
// ---------------------------------------------------------------------------
extern "C" void kernel_launch(void* const* d_in, const int* in_sizes, int n_in,
                              void* d_out, int out_size) {
    const float* x = (const float*)d_in[0];
    const int* ei = (const int*)d_in[1];      // int32 (JAX x64 disabled)
    const int* batch = (const int*)d_in[2];   // int32
    const float* Wrel = (const float*)d_in[3];
    const float* brel = (const float*)d_in[4];
    const float* Wroot = (const float*)d_in[5];
    const float* W1 = (const float*)d_in[6];
    const float* b1 = (const float*)d_in[7];
    const float* W2 = (const float*)d_in[8];
    const float* b2 = (const float*)d_in[9];
    float* out = (float*)d_out;

    cudaFuncSetAttribute(k_gemm_mma, cudaFuncAttributeMaxDynamicSharedMemorySize,
                         SM_TOTAL);

    uint32_t *xs, *h1, *h2;
    __half* wfp;
    cudaGetSymbolAddress((void**)&xs, g_xs);
    cudaGetSymbolAddress((void**)&h1, g_h1);
    cudaGetSymbolAddress((void**)&h2, g_h2);
    cudaGetSymbolAddress((void**)&wfp, g_Wf16);

    const int edge_blocks = (N_EDGES + 255) / 256;
    const int gather_blocks = (N_NODES + 15) / 16;   // 2 nodes per warp
    const int pool_blocks = (N_NODES + 8 * NODES_PER_WARP - 1) / (8 * NODES_PER_WARP);

    // Setup (zero + x-convert + weight prep in one kernel), then adjacency
    k_setup<<<SETUP_BLOCKS + 6, 256>>>(x, Wrel, Wroot);
    k_fill<<<edge_blocks, 256>>>(ei);

    // Layer 0: xs -> h1
    k_gather<<<gather_blocks, 256>>>(xs);
    k_gemm_mma<<<GRID_GEMM, GT, SM_TOTAL>>>(xs, wfp + 0 * 2 * IMG, brel, h1);
    // Layer 1: h1 -> h2
    k_gather<<<gather_blocks, 256>>>(h1);
    k_gemm_mma<<<GRID_GEMM, GT, SM_TOTAL>>>(h1, wfp + 1 * 2 * IMG, brel + D, h2);
    // Layer 2: h2 -> h1
    k_gather<<<gather_blocks, 256>>>(h2);
    k_gemm_mma<<<GRID_GEMM, GT, SM_TOTAL>>>(h2, wfp + 2 * 2 * IMG, brel + 2 * D, h1);

    // Pool + head
    k_pool<<<pool_blocks, 256>>>(h1, batch);
    k_head<<<N_GRAPHS, 128>>>(W1, b1, W2, b2, out);
}